// round 16
// baseline (speedup 1.0000x reference)
#include <cuda_runtime.h>
#include <cuda_bf16.h>
#include <math.h>
#include <cstdint>
#include <stdint.h>

#define NN 20000
#define NE 160000
#define NET 180000          // edges + self loops
#define NG 64
#define DMAX 1534
#define KMAX 512

// ---------------- scratch (device globals; no allocation) ----------------
__device__ float g_h  [(size_t)NN * KMAX];   // layer input h (fp32, <=512 dims)
__device__ float g_hag9[(size_t)NN * 16];    // layer-0 aggregated x (9 dims, fp32)
__device__ float g_agg[(size_t)NN * DMAX];   // GEMM out + bias + lrelu
__device__ float g_ssrc[NN], g_sdst[NN];
__device__ float g_cex[NET];                 // normalized alpha per CSR slot
__device__ float g_was[KMAX], g_wad[KMAX];   // W @ asrc, W @ adst (next layer)
__device__ int   g_indeg[NN];
__device__ int   g_off[NN + 1];
__device__ int   g_cur[NN];
__device__ int   g_csrc[NET];                // src per CSR slot
__device__ int   g_gs[NG + 1];               // node range per graph (batch sorted)
__device__ float g_gsum[NG * DMAX], g_gss[NG * DMAX];
__device__ float g_gmin[NG * DMAX], g_gmax[NG * DMAX];

// bf16 split planes (A = aggregated h row-major [M,K], B = W transposed [N,K])
__device__ __nv_bfloat16 g_ahi[(size_t)NN * KMAX], g_alo[(size_t)NN * KMAX];
__device__ __nv_bfloat16 g_bhi[(size_t)KMAX * DMAX], g_blo[(size_t)KMAX * DMAX];

// ---------------- helpers ----------------
__device__ __forceinline__ void mma_bf16(float* c,
        unsigned a0, unsigned a1, unsigned a2, unsigned a3,
        unsigned b0, unsigned b1) {
    asm volatile(
        "mma.sync.aligned.m16n8k16.row.col.f32.bf16.bf16.f32 "
        "{%0,%1,%2,%3}, {%4,%5,%6,%7}, {%8,%9}, {%0,%1,%2,%3};\n"
        : "+f"(c[0]), "+f"(c[1]), "+f"(c[2]), "+f"(c[3])
        : "r"(a0), "r"(a1), "r"(a2), "r"(a3), "r"(b0), "r"(b1));
}

__device__ __forceinline__ void cp16(unsigned saddr, const void* gaddr, int nbytes) {
    asm volatile("cp.async.cg.shared.global [%0], [%1], 16, %2;\n"
                 :: "r"(saddr), "l"(gaddr), "r"(nbytes));
}

// ---------------- CSR + graph-range setup ----------------
__global__ void k_zero_indeg() {
    int i = blockIdx.x * blockDim.x + threadIdx.x;
    if (i < NN) g_indeg[i] = 0;
}

__global__ void k_count(const int* __restrict__ ei) {
    int e = blockIdx.x * blockDim.x + threadIdx.x;
    if (e >= NET) return;
    int dst = (e < NE) ? ei[NE + e] : (e - NE);
    atomicAdd(&g_indeg[dst], 1);
}

__global__ void k_scan() {
    __shared__ int part[1024];
    int t = threadIdx.x;
    const int C = (NN + 1023) / 1024;
    int base = t * C;
    int s = 0;
    for (int i = 0; i < C; i++) { int idx = base + i; if (idx < NN) s += g_indeg[idx]; }
    part[t] = s; __syncthreads();
    for (int off = 1; off < 1024; off <<= 1) {
        int v = (t >= off) ? part[t - off] : 0;
        __syncthreads();
        part[t] += v;
        __syncthreads();
    }
    int ex = part[t] - s;
    for (int i = 0; i < C; i++) {
        int idx = base + i;
        if (idx < NN) { g_off[idx] = ex; g_cur[idx] = ex; ex += g_indeg[idx]; }
    }
    if (t == 1023) g_off[NN] = NET;
}

__global__ void k_fill(const int* __restrict__ ei) {
    int e = blockIdx.x * blockDim.x + threadIdx.x;
    if (e >= NET) return;
    int src, dst;
    if (e < NE) { src = ei[e]; dst = ei[NE + e]; }
    else        { src = dst = e - NE; }
    int pos = atomicAdd(&g_cur[dst], 1);
    g_csrc[pos] = src;
}

__global__ void k_granges(const int* __restrict__ batch) {
    int i = blockIdx.x * blockDim.x + threadIdx.x;
    if (i >= NN) return;
    int b = batch[i];
    if (i == 0) { for (int g = 0; g <= b; g++) g_gs[g] = 0; }
    else {
        int pb = batch[i - 1];
        if (pb != b) for (int g = pb + 1; g <= b; g++) g_gs[g] = i;
    }
    if (i == NN - 1) { for (int g = b + 1; g <= NG; g++) g_gs[g] = NN; }
}

// ---------------- was/wad = W @ asrc, W @ adst ----------------
__global__ void k_wvec(const float* __restrict__ W,
                       const float* __restrict__ asrc,
                       const float* __restrict__ adst, int din, int dout) {
    int gt = blockIdx.x * blockDim.x + threadIdx.x;
    int k = gt >> 5, lane = gt & 31;
    if (k >= din) return;
    const float* row = W + (size_t)k * dout;
    float a = 0.f, b = 0.f;
    for (int n = lane; n < dout; n += 32) {
        float w = row[n];
        a += w * asrc[n];
        b += w * adst[n];
    }
#pragma unroll
    for (int o = 16; o > 0; o >>= 1) {
        a += __shfl_down_sync(0xffffffff, a, o);
        b += __shfl_down_sync(0xffffffff, b, o);
    }
    if (lane == 0) { g_was[k] = a; g_wad[k] = b; }
}

// ---------------- weight split + transpose:  W[K,N] -> WT_hi/lo[N,K] ----------------
__global__ void k_splitWT(const float* __restrict__ W,
                          __nv_bfloat16* __restrict__ hiT,
                          __nv_bfloat16* __restrict__ loT, int K, int N) {
    int i = blockIdx.x * blockDim.x + threadIdx.x;
    if (i >= K * N) return;
    int k = i / N, n = i % N;
    float v = W[i];
    __nv_bfloat16 h = __float2bfloat16_rn(v);
    hiT[(size_t)n * K + k] = h;
    loT[(size_t)n * K + k] = __float2bfloat16_rn(v - __bfloat162float(h));
}

// layer-0 attention dots on x (9 dims)
__global__ void k_sdots(const float* __restrict__ h, int din) {
    int gt = blockIdx.x * blockDim.x + threadIdx.x;
    int w = gt >> 5, lane = gt & 31;
    if (w >= NN) return;
    const float* row = h + (size_t)w * din;
    float a = 0.f, b = 0.f;
    for (int c = lane; c < din; c += 32) {
        float v = row[c];
        a += v * g_was[c];
        b += v * g_wad[c];
    }
#pragma unroll
    for (int o = 16; o > 0; o >>= 1) {
        a += __shfl_down_sync(0xffffffff, a, o);
        b += __shfl_down_sync(0xffffffff, b, o);
    }
    if (lane == 0) { g_ssrc[w] = a; g_sdst[w] = b; }
}

// CSR-fused edge softmax: one warp per dst node. Writes NORMALIZED alpha.
__global__ void k_soft() {
    int gt = blockIdx.x * blockDim.x + threadIdx.x;
    int v = gt >> 5, lane = gt & 31;
    if (v >= NN) return;
    int beg = g_off[v], end = g_off[v + 1];
    float sd = g_sdst[v];
    float mx = -3.0e38f;
    for (int j = beg + lane; j < end; j += 32) {
        float sc = g_ssrc[g_csrc[j]] + sd;
        sc = (sc > 0.f) ? sc : 0.2f * sc;
        mx = fmaxf(mx, sc);
    }
#pragma unroll
    for (int o = 16; o > 0; o >>= 1)
        mx = fmaxf(mx, __shfl_xor_sync(0xffffffff, mx, o));
    float sum = 0.f;
    for (int j = beg + lane; j < end; j += 32) {
        float sc = g_ssrc[g_csrc[j]] + sd;
        sc = (sc > 0.f) ? sc : 0.2f * sc;
        float ex = expf(sc - mx);
        g_cex[j] = ex;
        sum += ex;
    }
#pragma unroll
    for (int o = 16; o > 0; o >>= 1)
        sum += __shfl_xor_sync(0xffffffff, sum, o);
    float inv = 1.f / (sum + 1e-16f);
    for (int j = beg + lane; j < end; j += 32) g_cex[j] *= inv;
}

// gather-aggregate h by dst via CSR (din dims).
// mode 0: fp32 to g_hag9 (layer 0). mode 1: bf16 split planes.
__global__ __launch_bounds__(256) void k_agg(const float* __restrict__ h,
                                             int din, int mode) {
    int v = blockIdx.x;
    int c = blockIdx.y * 256 + threadIdx.x;
    int beg = g_off[v], end = g_off[v + 1];
    __shared__ float s_a[64];
    __shared__ int   s_s[64];
    float acc = 0.f;
    for (int j0 = beg; j0 < end; j0 += 64) {
        int n = min(64, end - j0);
        __syncthreads();
        if (threadIdx.x < n) {
            s_a[threadIdx.x] = g_cex[j0 + threadIdx.x];
            s_s[threadIdx.x] = g_csrc[j0 + threadIdx.x];
        }
        __syncthreads();
        if (c < din) {
            for (int j = 0; j < n; j++)
                acc += s_a[j] * h[(size_t)s_s[j] * din + c];
        }
    }
    if (c < din) {
        if (mode == 0) {
            g_hag9[(size_t)v * 16 + c] = acc;
        } else {
            __nv_bfloat16 hi = __float2bfloat16_rn(acc);
            g_ahi[(size_t)v * din + c] = hi;
            g_alo[(size_t)v * din + c] = __float2bfloat16_rn(acc - __bfloat162float(hi));
        }
    }
}

// ---------------- GEMMs ----------------
// layer 0: aggx[9] @ W0[9,128] + b, lrelu.
__global__ void k_gemm0(const float* __restrict__ W, const float* __restrict__ bias) {
    __shared__ float xs[9];
    int n = blockIdx.x;
    int c = threadIdx.x;
    if (c < 9) xs[c] = g_hag9[(size_t)n * 16 + c];
    __syncthreads();
    float a = 0.f;
#pragma unroll
    for (int k = 0; k < 9; k++) a += xs[k] * W[k * 128 + c];
    a += bias[c];
    a = (a > 0.f) ? a : 0.01f * a;
    g_agg[(size_t)n * 128 + c] = a;
}

// Tensor-core GEMM with bf16-split-2, cp.async 2-stage pipeline.
// g_agg[M,N] = lrelu(A[M,K] @ B[K,N] + bias); A = hagg splits, B = W splits [N,K].
#define PLN (128 * 40)
__global__ __launch_bounds__(256) void k_mma(int N, int K,
                                             const float* __restrict__ bias) {
    extern __shared__ __nv_bfloat16 sm[];
    const int tid  = threadIdx.x;
    const int lane = tid & 31;
    const int wid  = tid >> 5;
    const int wm   = wid >> 2;          // 0..1 (64 rows)
    const int wn   = wid & 3;           // 0..3 (32 cols)
    const int gid  = lane >> 2;         // 0..7
    const int qid  = lane & 3;          // 0..3

    const int brow = blockIdx.y * 128;
    const int bcol = blockIdx.x * 128;
    const int M = NN;

    float acc[4][4][4];
#pragma unroll
    for (int i = 0; i < 4; i++)
#pragma unroll
        for (int j = 0; j < 4; j++)
#pragma unroll
            for (int v = 0; v < 4; v++) acc[i][j][v] = 0.f;

    const int l_r = tid >> 1, l_c = (tid & 1) << 4;   // element units
    const int arow_ok = (brow + l_r < M) ? 16 : 0;
    const int brow_ok = (bcol + l_r < N) ? 16 : 0;
    const size_t a_g = (size_t)(brow + l_r) * K + l_c;
    const size_t b_g = (size_t)(bcol + l_r) * K + l_c;
    unsigned sbase;
    {
        unsigned long long p = __cvta_generic_to_shared(sm);
        sbase = (unsigned)p;
    }
    const unsigned s_off = (unsigned)(l_r * 40 + l_c) * 2;

    const int nk = K >> 5;
    {
        cp16(sbase + 0 * PLN * 2 + s_off,      g_ahi + a_g,     arow_ok);
        cp16(sbase + 0 * PLN * 2 + s_off + 16, g_ahi + a_g + 8, arow_ok);
        cp16(sbase + 1 * PLN * 2 + s_off,      g_alo + a_g,     arow_ok);
        cp16(sbase + 1 * PLN * 2 + s_off + 16, g_alo + a_g + 8, arow_ok);
        cp16(sbase + 2 * PLN * 2 + s_off,      g_bhi + b_g,     brow_ok);
        cp16(sbase + 2 * PLN * 2 + s_off + 16, g_bhi + b_g + 8, brow_ok);
        cp16(sbase + 3 * PLN * 2 + s_off,      g_blo + b_g,     brow_ok);
        cp16(sbase + 3 * PLN * 2 + s_off + 16, g_blo + b_g + 8, brow_ok);
        asm volatile("cp.async.commit_group;\n");
    }

    int buf = 0;
    for (int kt = 0; kt < nk; kt++) {
        if (kt + 1 < nk) {
            int k0 = (kt + 1) << 5;
            unsigned sb = sbase + (unsigned)((buf ^ 1) * 4 * PLN) * 2 + s_off;
            cp16(sb + 0 * PLN * 2,      g_ahi + a_g + k0,     arow_ok);
            cp16(sb + 0 * PLN * 2 + 16, g_ahi + a_g + k0 + 8, arow_ok);
            cp16(sb + 1 * PLN * 2,      g_alo + a_g + k0,     arow_ok);
            cp16(sb + 1 * PLN * 2 + 16, g_alo + a_g + k0 + 8, arow_ok);
            cp16(sb + 2 * PLN * 2,      g_bhi + b_g + k0,     brow_ok);
            cp16(sb + 2 * PLN * 2 + 16, g_bhi + b_g + k0 + 8, brow_ok);
            cp16(sb + 3 * PLN * 2,      g_blo + b_g + k0,     brow_ok);
            cp16(sb + 3 * PLN * 2 + 16, g_blo + b_g + k0 + 8, brow_ok);
            asm volatile("cp.async.commit_group;\n");
            asm volatile("cp.async.wait_group 1;\n");
        } else {
            asm volatile("cp.async.wait_group 0;\n");
        }
        __syncthreads();

        const __nv_bfloat16* Ah = sm + (buf * 4 + 0) * PLN;
        const __nv_bfloat16* Al = sm + (buf * 4 + 1) * PLN;
        const __nv_bfloat16* Bh = sm + (buf * 4 + 2) * PLN;
        const __nv_bfloat16* Bl = sm + (buf * 4 + 3) * PLN;

#pragma unroll
        for (int ks = 0; ks < 2; ks++) {
            const int ac = ks * 16 + qid * 2;
            unsigned ah[4][4], al[4][4];
#pragma unroll
            for (int mt = 0; mt < 4; mt++) {
                int ar = wm * 64 + mt * 16 + gid;
                ah[mt][0] = *(const unsigned*)(Ah + ar * 40 + ac);
                ah[mt][1] = *(const unsigned*)(Ah + (ar + 8) * 40 + ac);
                ah[mt][2] = *(const unsigned*)(Ah + ar * 40 + ac + 8);
                ah[mt][3] = *(const unsigned*)(Ah + (ar + 8) * 40 + ac + 8);
                al[mt][0] = *(const unsigned*)(Al + ar * 40 + ac);
                al[mt][1] = *(const unsigned*)(Al + (ar + 8) * 40 + ac);
                al[mt][2] = *(const unsigned*)(Al + ar * 40 + ac + 8);
                al[mt][3] = *(const unsigned*)(Al + (ar + 8) * 40 + ac + 8);
            }
#pragma unroll
            for (int nt = 0; nt < 4; nt++) {
                int nb = wn * 32 + nt * 8 + gid;
                unsigned bh0 = *(const unsigned*)(Bh + nb * 40 + ac);
                unsigned bh1 = *(const unsigned*)(Bh + nb * 40 + ac + 8);
                unsigned bl0 = *(const unsigned*)(Bl + nb * 40 + ac);
                unsigned bl1 = *(const unsigned*)(Bl + nb * 40 + ac + 8);
#pragma unroll
                for (int mt = 0; mt < 4; mt++) {
                    mma_bf16(acc[mt][nt], ah[mt][0], ah[mt][1], ah[mt][2], ah[mt][3], bh0, bh1);
                    mma_bf16(acc[mt][nt], ah[mt][0], ah[mt][1], ah[mt][2], ah[mt][3], bl0, bl1);
                    mma_bf16(acc[mt][nt], al[mt][0], al[mt][1], al[mt][2], al[mt][3], bh0, bh1);
                }
            }
        }
        __syncthreads();
        buf ^= 1;
    }

    // epilogue: bias + LeakyReLU(0.01), store to g_agg
#pragma unroll
    for (int mt = 0; mt < 4; mt++) {
        int r0 = brow + wm * 64 + mt * 16 + gid;
        int r1 = r0 + 8;
#pragma unroll
        for (int nt = 0; nt < 4; nt++) {
            int cb = bcol + wn * 32 + nt * 8 + qid * 2;
            if (cb < N) {
                float2 bv = *(const float2*)&bias[cb];
                float v0 = acc[mt][nt][0] + bv.x;
                float v1 = acc[mt][nt][1] + bv.y;
                float v2 = acc[mt][nt][2] + bv.x;
                float v3 = acc[mt][nt][3] + bv.y;
                v0 = (v0 > 0.f) ? v0 : 0.01f * v0;
                v1 = (v1 > 0.f) ? v1 : 0.01f * v1;
                v2 = (v2 > 0.f) ? v2 : 0.01f * v2;
                v3 = (v3 > 0.f) ? v3 : 0.01f * v3;
                if (r0 < M) *(float2*)&g_agg[(size_t)r0 * N + cb] = make_float2(v0, v1);
                if (r1 < M) *(float2*)&g_agg[(size_t)r1 * N + cb] = make_float2(v2, v3);
            }
        }
    }
}

// GraphNorm pass 1: per-(graph, channel) sum, sumsq, min, max.
// Also zeroes g_ssrc/g_sdst (grid-strided) when zeroDots != 0.
__global__ void k_norm1(int dout, int zeroDots) {
    if (zeroDots) {
        int total = gridDim.x * gridDim.y * 256;
        int gt = (blockIdx.x * gridDim.y + blockIdx.y) * 256 + threadIdx.x;
        for (int i = gt; i < NN; i += total) { g_ssrc[i] = 0.f; g_sdst[i] = 0.f; }
    }
    int g = blockIdx.x;
    int c = blockIdx.y * 256 + threadIdx.x;
    if (c >= dout) return;
    int s0 = g_gs[g], s1 = g_gs[g + 1];
    float s = 0.f, ss = 0.f, mn = 3.4e38f, mx = -3.4e38f;
    for (int n = s0; n < s1; n++) {
        float v = g_agg[(size_t)n * dout + c];
        s += v; ss += v * v;
        mn = fminf(mn, v); mx = fmaxf(mx, v);
    }
    g_gsum[g * dout + c] = s;
    g_gss [g * dout + c] = ss;
    g_gmin[g * dout + c] = mn;
    g_gmax[g * dout + c] = mx;
}

// GraphNorm pass 2 (layers 0-2): normalize, write fp32 h for next layer,
// and accumulate the NEXT layer's attention dots (g_was/g_wad preloaded).
__global__ void k_norm2(const int* __restrict__ batch,
                        const float* __restrict__ gw,
                        const float* __restrict__ bt,
                        const float* __restrict__ ms, int dout) {
    __shared__ float rs[8], rd[8];
    int n = blockIdx.x;
    int c = blockIdx.y * 256 + threadIdx.x;
    int lane = threadIdx.x & 31, wrp = threadIdx.x >> 5;
    float a = 0.f, b = 0.f;
    if (c < dout) {
        int g = batch[n];
        float cnt  = (float)(g_gs[g + 1] - g_gs[g]);
        float mean = g_gsum[g * dout + c] / cnt;
        float msv  = ms[c];
        float var  = g_gss[g * dout + c] / cnt - mean * mean * (2.f * msv - msv * msv);
        float v0 = g_agg[(size_t)n * dout + c] - msv * mean;
        float v = v0 * rsqrtf(var + 1e-5f) * gw[c] + bt[c];
        g_h[(size_t)n * dout + c] = v;
        a = v * g_was[c];
        b = v * g_wad[c];
    }
#pragma unroll
    for (int o = 16; o > 0; o >>= 1) {
        a += __shfl_down_sync(0xffffffff, a, o);
        b += __shfl_down_sync(0xffffffff, b, o);
    }
    if (lane == 0) { rs[wrp] = a; rd[wrp] = b; }
    __syncthreads();
    if (threadIdx.x == 0) {
        float sa = 0.f, sb = 0.f;
#pragma unroll
        for (int i = 0; i < 8; i++) { sa += rs[i]; sb += rd[i]; }
        atomicAdd(&g_ssrc[n], sa);
        atomicAdd(&g_sdst[n], sb);
    }
}

// Final layer: GraphNorm + readout in closed form (affine map on agg stats).
__global__ void k_final(const float* __restrict__ gw,
                        const float* __restrict__ bt,
                        const float* __restrict__ ms,
                        float* __restrict__ out) {
    int g = blockIdx.x;
    int c = blockIdx.y * 256 + threadIdx.x;
    if (c >= DMAX) return;
    float cnt  = (float)(g_gs[g + 1] - g_gs[g]);
    float mean = g_gsum[g * DMAX + c] / cnt;
    float msv  = ms[c];
    float var  = g_gss[g * DMAX + c] / cnt - mean * mean * (2.f * msv - msv * msv);
    float rstd = rsqrtf(var + 1e-5f);
    float gwc  = gw[c], btc = bt[c];
    float vm = (mean - msv * mean) * rstd * gwc + btc;
    float sel = (gwc >= 0.f) ? g_gmax[g * DMAX + c] : g_gmin[g * DMAX + c];
    float vx = (sel - msv * mean) * rstd * gwc + btc;
    out[g * 2 * DMAX + c]        = vm;
    out[g * 2 * DMAX + DMAX + c] = vx;
}

// ---------------- driver ----------------
extern "C" void kernel_launch(void* const* d_in, const int* in_sizes, int n_in,
                              void* d_out, int out_size) {
    const float* x     = (const float*)d_in[0];
    const int*   ei    = (const int*)  d_in[1];
    const int*   batch = (const int*)  d_in[2];
    const float *W[4], *asrc[4], *adst[4], *bb[4], *gw[4], *bt[4], *ms[4];
    for (int l = 0; l < 4; l++) {
        W[l]    = (const float*)d_in[3 + 7 * l + 0];
        asrc[l] = (const float*)d_in[3 + 7 * l + 1];
        adst[l] = (const float*)d_in[3 + 7 * l + 2];
        bb[l]   = (const float*)d_in[3 + 7 * l + 3];
        gw[l]   = (const float*)d_in[3 + 7 * l + 4];
        bt[l]   = (const float*)d_in[3 + 7 * l + 5];
        ms[l]   = (const float*)d_in[3 + 7 * l + 6];
    }
    const int dims[5] = {9, 128, 256, 512, 1534};

    __nv_bfloat16 *bhi, *blo;
    float* gh;
    cudaGetSymbolAddress((void**)&bhi, g_bhi);
    cudaGetSymbolAddress((void**)&blo, g_blo);
    cudaGetSymbolAddress((void**)&gh,  g_h);

    const int mma_smem = 2 * 4 * PLN * 2;   // 81920 bytes
    cudaFuncSetAttribute(k_mma, cudaFuncAttributeMaxDynamicSharedMemorySize, mma_smem);

    // topology setup (same every call; deterministic work)
    k_zero_indeg<<<(NN + 255) / 256, 256>>>();
    k_count     <<<(NET + 255) / 256, 256>>>(ei);
    k_scan      <<<1, 1024>>>();
    k_fill      <<<(NET + 255) / 256, 256>>>(ei);
    k_granges   <<<(NN + 255) / 256, 256>>>(batch);

    // layer 0 attention dots come from x directly
    k_wvec <<<(dims[0] * 32 + 255) / 256, 256>>>(W[0], asrc[0], adst[0], dims[0], dims[1]);
    k_sdots<<<(NN * 32 + 255) / 256, 256>>>(x, dims[0]);

    for (int l = 0; l < 4; l++) {
        int din = dims[l], dout = dims[l + 1];
        const float* hin = (l == 0) ? x : gh;

        k_soft<<<(NN * 32 + 255) / 256, 256>>>();

        int nych = (din + 255) / 256;
        k_agg<<<dim3(NN, nych), 256>>>(hin, din, (l == 0) ? 0 : 1);

        if (l == 0) {
            k_gemm0<<<NN, 128>>>(W[0], bb[0]);
        } else {
            int nb = din * dout;
            k_splitWT<<<(nb + 255) / 256, 256>>>(W[l], bhi, blo, din, dout);
            dim3 grid((dout + 127) / 128, (NN + 127) / 128);
            k_mma<<<grid, 256, mma_smem>>>(dout, din, bb[l]);
        }
        int nch = (dout + 255) / 256;
        k_norm1<<<dim3(NG, nch), 256>>>(dout, (l < 3) ? 1 : 0);
        if (l < 3) {
            // was/wad for the NEXT layer, then norm2 fuses normalize + dots
            k_wvec <<<(dout * 32 + 255) / 256, 256>>>(W[l + 1], asrc[l + 1], adst[l + 1],
                                                      dout, dims[l + 2]);
            k_norm2<<<dim3(NN, nch), 256>>>(batch, gw[l], bt[l], ms[l], dout);
        }
    }
    k_final<<<dim3(NG, (DMAX + 255) / 256), 256>>>(gw[3], bt[3], ms[3], (float*)d_out);
}

// round 17
// speedup vs baseline: 1.0149x; 1.0149x over previous
#include <cuda_runtime.h>
#include <cuda_bf16.h>
#include <math.h>
#include <cstdint>
#include <stdint.h>

#define NN 20000
#define NE 160000
#define NET 180000          // edges + self loops
#define NG 64
#define DMAX 1534
#define KMAX 512

// ---------------- scratch (device globals; no allocation) ----------------
__device__ float g_h  [(size_t)NN * KMAX];   // layer input h (fp32, <=512 dims)
__device__ float g_hag9[(size_t)NN * 16];    // layer-0 aggregated x (9 dims, fp32)
__device__ float g_agg[(size_t)NN * DMAX];   // GEMM out + bias + lrelu
__device__ float g_ssrc[NN], g_sdst[NN];
__device__ float g_cex[NET];                 // normalized alpha per CSR slot
__device__ float g_was[KMAX], g_wad[KMAX];   // W @ asrc, W @ adst
__device__ int   g_indeg[NN];
__device__ int   g_off[NN + 1];
__device__ int   g_cur[NN];
__device__ int   g_csrc[NET];                // src per CSR slot
__device__ int   g_gs[NG + 1];               // node range per graph (batch sorted)
__device__ float g_gsum[NG * DMAX], g_gss[NG * DMAX];
__device__ float g_gmin[NG * DMAX], g_gmax[NG * DMAX];

// bf16 split planes (A = aggregated h row-major [M,K], B = W transposed [N,K])
__device__ __nv_bfloat16 g_ahi[(size_t)NN * KMAX], g_alo[(size_t)NN * KMAX];
__device__ __nv_bfloat16 g_bhi[(size_t)KMAX * DMAX], g_blo[(size_t)KMAX * DMAX];

// ---------------- helpers ----------------
__device__ __forceinline__ void mma_bf16(float* c,
        unsigned a0, unsigned a1, unsigned a2, unsigned a3,
        unsigned b0, unsigned b1) {
    asm volatile(
        "mma.sync.aligned.m16n8k16.row.col.f32.bf16.bf16.f32 "
        "{%0,%1,%2,%3}, {%4,%5,%6,%7}, {%8,%9}, {%0,%1,%2,%3};\n"
        : "+f"(c[0]), "+f"(c[1]), "+f"(c[2]), "+f"(c[3])
        : "r"(a0), "r"(a1), "r"(a2), "r"(a3), "r"(b0), "r"(b1));
}

__device__ __forceinline__ void cp16(unsigned saddr, const void* gaddr, int nbytes) {
    asm volatile("cp.async.cg.shared.global [%0], [%1], 16, %2;\n"
                 :: "r"(saddr), "l"(gaddr), "r"(nbytes));
}

// ---------------- CSR + graph-range setup ----------------
__global__ void k_zero_indeg() {
    int i = blockIdx.x * blockDim.x + threadIdx.x;
    if (i < NN) g_indeg[i] = 0;
}

__global__ void k_count(const int* __restrict__ ei) {
    int e = blockIdx.x * blockDim.x + threadIdx.x;
    if (e >= NET) return;
    int dst = (e < NE) ? ei[NE + e] : (e - NE);
    atomicAdd(&g_indeg[dst], 1);
}

__global__ void k_scan() {
    __shared__ int part[1024];
    int t = threadIdx.x;
    const int C = (NN + 1023) / 1024;
    int base = t * C;
    int s = 0;
    for (int i = 0; i < C; i++) { int idx = base + i; if (idx < NN) s += g_indeg[idx]; }
    part[t] = s; __syncthreads();
    for (int off = 1; off < 1024; off <<= 1) {
        int v = (t >= off) ? part[t - off] : 0;
        __syncthreads();
        part[t] += v;
        __syncthreads();
    }
    int ex = part[t] - s;
    for (int i = 0; i < C; i++) {
        int idx = base + i;
        if (idx < NN) { g_off[idx] = ex; g_cur[idx] = ex; ex += g_indeg[idx]; }
    }
    if (t == 1023) g_off[NN] = NET;
}

__global__ void k_fill(const int* __restrict__ ei) {
    int e = blockIdx.x * blockDim.x + threadIdx.x;
    if (e >= NET) return;
    int src, dst;
    if (e < NE) { src = ei[e]; dst = ei[NE + e]; }
    else        { src = dst = e - NE; }
    int pos = atomicAdd(&g_cur[dst], 1);
    g_csrc[pos] = src;
}

__global__ void k_granges(const int* __restrict__ batch) {
    int i = blockIdx.x * blockDim.x + threadIdx.x;
    if (i >= NN) return;
    int b = batch[i];
    if (i == 0) { for (int g = 0; g <= b; g++) g_gs[g] = 0; }
    else {
        int pb = batch[i - 1];
        if (pb != b) for (int g = pb + 1; g <= b; g++) g_gs[g] = i;
    }
    if (i == NN - 1) { for (int g = b + 1; g <= NG; g++) g_gs[g] = NN; }
}

// ---------------- was/wad = W @ asrc, W @ adst ----------------
__global__ void k_wvec(const float* __restrict__ W,
                       const float* __restrict__ asrc,
                       const float* __restrict__ adst, int din, int dout) {
    int gt = blockIdx.x * blockDim.x + threadIdx.x;
    int k = gt >> 5, lane = gt & 31;
    if (k >= din) return;
    const float* row = W + (size_t)k * dout;
    float a = 0.f, b = 0.f;
    for (int n = lane; n < dout; n += 32) {
        float w = row[n];
        a += w * asrc[n];
        b += w * adst[n];
    }
#pragma unroll
    for (int o = 16; o > 0; o >>= 1) {
        a += __shfl_down_sync(0xffffffff, a, o);
        b += __shfl_down_sync(0xffffffff, b, o);
    }
    if (lane == 0) { g_was[k] = a; g_wad[k] = b; }
}

// ---------------- weight split + transpose:  W[K,N] -> WT_hi/lo[N,K] ----------------
__global__ void k_splitWT(const float* __restrict__ W,
                          __nv_bfloat16* __restrict__ hiT,
                          __nv_bfloat16* __restrict__ loT, int K, int N) {
    int i = blockIdx.x * blockDim.x + threadIdx.x;
    if (i >= K * N) return;
    int k = i / N, n = i % N;
    float v = W[i];
    __nv_bfloat16 h = __float2bfloat16_rn(v);
    hiT[(size_t)n * K + k] = h;
    loT[(size_t)n * K + k] = __float2bfloat16_rn(v - __bfloat162float(h));
}

// per-node attention dot products on h (din dims)
__global__ void k_sdots(const float* __restrict__ h, int din) {
    int gt = blockIdx.x * blockDim.x + threadIdx.x;
    int w = gt >> 5, lane = gt & 31;
    if (w >= NN) return;
    const float* row = h + (size_t)w * din;
    float a = 0.f, b = 0.f;
    for (int c = lane; c < din; c += 32) {
        float v = row[c];
        a += v * g_was[c];
        b += v * g_wad[c];
    }
#pragma unroll
    for (int o = 16; o > 0; o >>= 1) {
        a += __shfl_down_sync(0xffffffff, a, o);
        b += __shfl_down_sync(0xffffffff, b, o);
    }
    if (lane == 0) { g_ssrc[w] = a; g_sdst[w] = b; }
}

// CSR-fused edge softmax: one warp per dst node. Writes NORMALIZED alpha.
__global__ void k_soft() {
    int gt = blockIdx.x * blockDim.x + threadIdx.x;
    int v = gt >> 5, lane = gt & 31;
    if (v >= NN) return;
    int beg = g_off[v], end = g_off[v + 1];
    float sd = g_sdst[v];
    float mx = -3.0e38f;
    for (int j = beg + lane; j < end; j += 32) {
        float sc = g_ssrc[g_csrc[j]] + sd;
        sc = (sc > 0.f) ? sc : 0.2f * sc;
        mx = fmaxf(mx, sc);
    }
#pragma unroll
    for (int o = 16; o > 0; o >>= 1)
        mx = fmaxf(mx, __shfl_xor_sync(0xffffffff, mx, o));
    float sum = 0.f;
    for (int j = beg + lane; j < end; j += 32) {
        float sc = g_ssrc[g_csrc[j]] + sd;
        sc = (sc > 0.f) ? sc : 0.2f * sc;
        float ex = expf(sc - mx);
        g_cex[j] = ex;
        sum += ex;
    }
#pragma unroll
    for (int o = 16; o > 0; o >>= 1)
        sum += __shfl_xor_sync(0xffffffff, sum, o);
    float inv = 1.f / (sum + 1e-16f);
    for (int j = beg + lane; j < end; j += 32) g_cex[j] *= inv;
}

// gather-aggregate h by dst via CSR (din dims).
// mode 0: fp32 to g_hag9 (layer 0). mode 1: bf16 split planes.
__global__ __launch_bounds__(256) void k_agg(const float* __restrict__ h,
                                             int din, int mode) {
    int v = blockIdx.x;
    int c = blockIdx.y * 256 + threadIdx.x;
    int beg = g_off[v], end = g_off[v + 1];
    __shared__ float s_a[64];
    __shared__ int   s_s[64];
    float acc = 0.f;
    for (int j0 = beg; j0 < end; j0 += 64) {
        int n = min(64, end - j0);
        __syncthreads();
        if (threadIdx.x < n) {
            s_a[threadIdx.x] = g_cex[j0 + threadIdx.x];
            s_s[threadIdx.x] = g_csrc[j0 + threadIdx.x];
        }
        __syncthreads();
        if (c < din) {
            for (int j = 0; j < n; j++)
                acc += s_a[j] * h[(size_t)s_s[j] * din + c];
        }
    }
    if (c < din) {
        if (mode == 0) {
            g_hag9[(size_t)v * 16 + c] = acc;
        } else {
            __nv_bfloat16 hi = __float2bfloat16_rn(acc);
            g_ahi[(size_t)v * din + c] = hi;
            g_alo[(size_t)v * din + c] = __float2bfloat16_rn(acc - __bfloat162float(hi));
        }
    }
}

// ---------------- GEMMs ----------------
// layer 0: aggx[9] @ W0[9,128] + b, lrelu.
__global__ void k_gemm0(const float* __restrict__ W, const float* __restrict__ bias) {
    __shared__ float xs[9];
    int n = blockIdx.x;
    int c = threadIdx.x;
    if (c < 9) xs[c] = g_hag9[(size_t)n * 16 + c];
    __syncthreads();
    float a = 0.f;
#pragma unroll
    for (int k = 0; k < 9; k++) a += xs[k] * W[k * 128 + c];
    a += bias[c];
    a = (a > 0.f) ? a : 0.01f * a;
    g_agg[(size_t)n * 128 + c] = a;
}

// Tensor-core GEMM with bf16-split-2, cp.async 3-stage pipeline (1 barrier/iter).
// g_agg[M,N] = lrelu(A[M,K] @ B[K,N] + bias); A = hagg splits, B = W splits [N,K].
#define PLN (128 * 40)
__global__ __launch_bounds__(256) void k_mma(int N, int K,
                                             const float* __restrict__ bias) {
    extern __shared__ __nv_bfloat16 sm[];
    const int tid  = threadIdx.x;
    const int lane = tid & 31;
    const int wid  = tid >> 5;
    const int wm   = wid >> 2;          // 0..1 (64 rows)
    const int wn   = wid & 3;           // 0..3 (32 cols)
    const int gid  = lane >> 2;         // 0..7
    const int qid  = lane & 3;          // 0..3

    const int brow = blockIdx.y * 128;
    const int bcol = blockIdx.x * 128;
    const int M = NN;

    float acc[4][4][4];
#pragma unroll
    for (int i = 0; i < 4; i++)
#pragma unroll
        for (int j = 0; j < 4; j++)
#pragma unroll
            for (int v = 0; v < 4; v++) acc[i][j][v] = 0.f;

    const int l_r = tid >> 1, l_c = (tid & 1) << 4;   // element units
    const int arow_ok = (brow + l_r < M) ? 16 : 0;
    const int brow_ok = (bcol + l_r < N) ? 16 : 0;
    const size_t a_g = (size_t)(brow + l_r) * K + l_c;
    const size_t b_g = (size_t)(bcol + l_r) * K + l_c;
    unsigned sbase;
    {
        unsigned long long p = __cvta_generic_to_shared(sm);
        sbase = (unsigned)p;
    }
    const unsigned s_off = (unsigned)(l_r * 40 + l_c) * 2;

    const int nk = K >> 5;   // >= 4 for all layers here

#define PREFETCH(kt, st)                                                     \
    {                                                                        \
        int k0 = (kt) << 5;                                                  \
        unsigned sb = sbase + (unsigned)((st) * 4 * PLN) * 2 + s_off;        \
        cp16(sb + 0 * PLN * 2,      g_ahi + a_g + k0,     arow_ok);          \
        cp16(sb + 0 * PLN * 2 + 16, g_ahi + a_g + k0 + 8, arow_ok);          \
        cp16(sb + 1 * PLN * 2,      g_alo + a_g + k0,     arow_ok);          \
        cp16(sb + 1 * PLN * 2 + 16, g_alo + a_g + k0 + 8, arow_ok);          \
        cp16(sb + 2 * PLN * 2,      g_bhi + b_g + k0,     brow_ok);          \
        cp16(sb + 2 * PLN * 2 + 16, g_bhi + b_g + k0 + 8, brow_ok);          \
        cp16(sb + 3 * PLN * 2,      g_blo + b_g + k0,     brow_ok);          \
        cp16(sb + 3 * PLN * 2 + 16, g_blo + b_g + k0 + 8, brow_ok);          \
        asm volatile("cp.async.commit_group;\n");                            \
    }

    PREFETCH(0, 0);
    PREFETCH(1, 1);

    int st = 0;   // stage of current kt (kt % 3)
    for (int kt = 0; kt < nk; kt++) {
        if (kt + 1 < nk) {
            asm volatile("cp.async.wait_group 1;\n");
        } else {
            asm volatile("cp.async.wait_group 0;\n");
        }
        __syncthreads();     // stage kt visible to all; compute kt-1 done on all
        if (kt + 2 < nk) {
            int st2 = st + 2; if (st2 >= 3) st2 -= 3;
            PREFETCH(kt + 2, st2);
        }

        const __nv_bfloat16* Ah = sm + (st * 4 + 0) * PLN;
        const __nv_bfloat16* Al = sm + (st * 4 + 1) * PLN;
        const __nv_bfloat16* Bh = sm + (st * 4 + 2) * PLN;
        const __nv_bfloat16* Bl = sm + (st * 4 + 3) * PLN;

#pragma unroll
        for (int ks = 0; ks < 2; ks++) {
            const int ac = ks * 16 + qid * 2;
            unsigned ah[4][4], al[4][4];
#pragma unroll
            for (int mt = 0; mt < 4; mt++) {
                int ar = wm * 64 + mt * 16 + gid;
                ah[mt][0] = *(const unsigned*)(Ah + ar * 40 + ac);
                ah[mt][1] = *(const unsigned*)(Ah + (ar + 8) * 40 + ac);
                ah[mt][2] = *(const unsigned*)(Ah + ar * 40 + ac + 8);
                ah[mt][3] = *(const unsigned*)(Ah + (ar + 8) * 40 + ac + 8);
                al[mt][0] = *(const unsigned*)(Al + ar * 40 + ac);
                al[mt][1] = *(const unsigned*)(Al + (ar + 8) * 40 + ac);
                al[mt][2] = *(const unsigned*)(Al + ar * 40 + ac + 8);
                al[mt][3] = *(const unsigned*)(Al + (ar + 8) * 40 + ac + 8);
            }
#pragma unroll
            for (int nt = 0; nt < 4; nt++) {
                int nb = wn * 32 + nt * 8 + gid;
                unsigned bh0 = *(const unsigned*)(Bh + nb * 40 + ac);
                unsigned bh1 = *(const unsigned*)(Bh + nb * 40 + ac + 8);
                unsigned bl0 = *(const unsigned*)(Bl + nb * 40 + ac);
                unsigned bl1 = *(const unsigned*)(Bl + nb * 40 + ac + 8);
#pragma unroll
                for (int mt = 0; mt < 4; mt++) {
                    mma_bf16(acc[mt][nt], ah[mt][0], ah[mt][1], ah[mt][2], ah[mt][3], bh0, bh1);
                    mma_bf16(acc[mt][nt], ah[mt][0], ah[mt][1], ah[mt][2], ah[mt][3], bl0, bl1);
                    mma_bf16(acc[mt][nt], al[mt][0], al[mt][1], al[mt][2], al[mt][3], bh0, bh1);
                }
            }
        }
        st++; if (st >= 3) st -= 3;
    }

    // epilogue: bias + LeakyReLU(0.01), store to g_agg
#pragma unroll
    for (int mt = 0; mt < 4; mt++) {
        int r0 = brow + wm * 64 + mt * 16 + gid;
        int r1 = r0 + 8;
#pragma unroll
        for (int nt = 0; nt < 4; nt++) {
            int cb = bcol + wn * 32 + nt * 8 + qid * 2;
            if (cb < N) {
                float2 bv = *(const float2*)&bias[cb];
                float v0 = acc[mt][nt][0] + bv.x;
                float v1 = acc[mt][nt][1] + bv.y;
                float v2 = acc[mt][nt][2] + bv.x;
                float v3 = acc[mt][nt][3] + bv.y;
                v0 = (v0 > 0.f) ? v0 : 0.01f * v0;
                v1 = (v1 > 0.f) ? v1 : 0.01f * v1;
                v2 = (v2 > 0.f) ? v2 : 0.01f * v2;
                v3 = (v3 > 0.f) ? v3 : 0.01f * v3;
                if (r0 < M) *(float2*)&g_agg[(size_t)r0 * N + cb] = make_float2(v0, v1);
                if (r1 < M) *(float2*)&g_agg[(size_t)r1 * N + cb] = make_float2(v2, v3);
            }
        }
    }
}

// GraphNorm pass 1: per-(graph, channel) sum, sumsq, min, max
__global__ void k_norm1(int dout) {
    int g = blockIdx.x;
    int c = blockIdx.y * 256 + threadIdx.x;
    if (c >= dout) return;
    int s0 = g_gs[g], s1 = g_gs[g + 1];
    float s = 0.f, ss = 0.f, mn = 3.4e38f, mx = -3.4e38f;
    for (int n = s0; n < s1; n++) {
        float v = g_agg[(size_t)n * dout + c];
        s += v; ss += v * v;
        mn = fminf(mn, v); mx = fmaxf(mx, v);
    }
    g_gsum[g * dout + c] = s;
    g_gss [g * dout + c] = ss;
    g_gmin[g * dout + c] = mn;
    g_gmax[g * dout + c] = mx;
}

// GraphNorm pass 2 (layers 0-2): normalize, write fp32 h for next layer.
__global__ void k_norm2(const int* __restrict__ batch,
                        const float* __restrict__ gw,
                        const float* __restrict__ bt,
                        const float* __restrict__ ms, int dout) {
    int n = blockIdx.x;
    int c = blockIdx.y * 256 + threadIdx.x;
    if (c >= dout) return;
    int g = batch[n];
    float cnt  = (float)(g_gs[g + 1] - g_gs[g]);
    float mean = g_gsum[g * dout + c] / cnt;
    float msv  = ms[c];
    float var  = g_gss[g * dout + c] / cnt - mean * mean * (2.f * msv - msv * msv);
    float v0 = g_agg[(size_t)n * dout + c] - msv * mean;
    float v = v0 * rsqrtf(var + 1e-5f) * gw[c] + bt[c];
    g_h[(size_t)n * dout + c] = v;
}

// Final layer: GraphNorm + readout in closed form (affine map on agg stats).
__global__ void k_final(const float* __restrict__ gw,
                        const float* __restrict__ bt,
                        const float* __restrict__ ms,
                        float* __restrict__ out) {
    int g = blockIdx.x;
    int c = blockIdx.y * 256 + threadIdx.x;
    if (c >= DMAX) return;
    float cnt  = (float)(g_gs[g + 1] - g_gs[g]);
    float mean = g_gsum[g * DMAX + c] / cnt;
    float msv  = ms[c];
    float var  = g_gss[g * DMAX + c] / cnt - mean * mean * (2.f * msv - msv * msv);
    float rstd = rsqrtf(var + 1e-5f);
    float gwc  = gw[c], btc = bt[c];
    float vm = (mean - msv * mean) * rstd * gwc + btc;
    float sel = (gwc >= 0.f) ? g_gmax[g * DMAX + c] : g_gmin[g * DMAX + c];
    float vx = (sel - msv * mean) * rstd * gwc + btc;
    out[g * 2 * DMAX + c]        = vm;
    out[g * 2 * DMAX + DMAX + c] = vx;
}

// ---------------- driver ----------------
extern "C" void kernel_launch(void* const* d_in, const int* in_sizes, int n_in,
                              void* d_out, int out_size) {
    const float* x     = (const float*)d_in[0];
    const int*   ei    = (const int*)  d_in[1];
    const int*   batch = (const int*)  d_in[2];
    const float *W[4], *asrc[4], *adst[4], *bb[4], *gw[4], *bt[4], *ms[4];
    for (int l = 0; l < 4; l++) {
        W[l]    = (const float*)d_in[3 + 7 * l + 0];
        asrc[l] = (const float*)d_in[3 + 7 * l + 1];
        adst[l] = (const float*)d_in[3 + 7 * l + 2];
        bb[l]   = (const float*)d_in[3 + 7 * l + 3];
        gw[l]   = (const float*)d_in[3 + 7 * l + 4];
        bt[l]   = (const float*)d_in[3 + 7 * l + 5];
        ms[l]   = (const float*)d_in[3 + 7 * l + 6];
    }
    const int dims[5] = {9, 128, 256, 512, 1534};

    __nv_bfloat16 *bhi, *blo;
    float* gh;
    cudaGetSymbolAddress((void**)&bhi, g_bhi);
    cudaGetSymbolAddress((void**)&blo, g_blo);
    cudaGetSymbolAddress((void**)&gh,  g_h);

    const int mma_smem = 3 * 4 * PLN * 2;   // 122880 bytes (3 stages)
    cudaFuncSetAttribute(k_mma, cudaFuncAttributeMaxDynamicSharedMemorySize, mma_smem);

    // topology setup (same every call; deterministic work)
    k_zero_indeg<<<(NN + 255) / 256, 256>>>();
    k_count     <<<(NET + 255) / 256, 256>>>(ei);
    k_scan      <<<1, 1024>>>();
    k_fill      <<<(NET + 255) / 256, 256>>>(ei);
    k_granges   <<<(NN + 255) / 256, 256>>>(batch);

    for (int l = 0; l < 4; l++) {
        int din = dims[l], dout = dims[l + 1];
        const float* hin = (l == 0) ? x : gh;

        k_wvec <<<(din * 32 + 255) / 256, 256>>>(W[l], asrc[l], adst[l], din, dout);
        k_sdots<<<(NN * 32 + 255) / 256, 256>>>(hin, din);
        k_soft <<<(NN * 32 + 255) / 256, 256>>>();

        int nych = (din + 255) / 256;
        k_agg<<<dim3(NN, nych), 256>>>(hin, din, (l == 0) ? 0 : 1);

        if (l == 0) {
            k_gemm0<<<NN, 128>>>(W[0], bb[0]);
        } else {
            int nb = din * dout;
            k_splitWT<<<(nb + 255) / 256, 256>>>(W[l], bhi, blo, din, dout);
            dim3 grid((dout + 127) / 128, (NN + 127) / 128);
            k_mma<<<grid, 256, mma_smem>>>(dout, din, bb[l]);
        }
        int nch = (dout + 255) / 256;
        k_norm1<<<dim3(NG, nch), 256>>>(dout);
        if (l < 3)
            k_norm2<<<dim3(NN, nch), 256>>>(batch, gw[l], bt[l], ms[l], dout);
    }
    k_final<<<dim3(NG, (DMAX + 255) / 256), 256>>>(gw[3], bt[3], ms[3], (float*)d_out);
}